// round 10
// baseline (speedup 1.0000x reference)
#include <cuda_runtime.h>

#define BB 64
#define NN 512
#define EPS 1e-10f

// Scratch (allocation-free rule: __device__ globals)
// Items at RELEVANCE-SORTED positions: {gain, disc, exp(score), lo_as_int}
// lo = first sorted position with strictly lower relevance.
__device__ float4   g_items[BB * NN];
__device__ float    g_rowScale[BB];     // ln2 / (idcg * (cnt+eps)) / B
__device__ float    g_accum = 0.0f;
__device__ unsigned g_count = 0u;

// ---------------- Kernel 1: ranks + sorted placement + row constants -----------
// grid (8, 64), 512 threads. Block q owns items [q*64, q*64+64).
// 8 threads/item, j = 8*jj + part (8 adjacent float2 addrs/warp -> conflict-free,
// broadcast across item-groups). Tie-break (j < i) via loop split.
// Histogram via warp ballots. Deterministic placement via same-rel scan.
__global__ __launch_bounds__(512, 2)
void lr_prep(const float* __restrict__ scores,
             const float* __restrict__ relevance) {
    const int q   = blockIdx.x;
    const int row = blockIdx.y;
    const int t   = threadIdx.x;

    __shared__ float2 sv[NN];           // {score, rel}
    __shared__ int    counts[5];
    __shared__ float  wred[16];

    if (t < 5) counts[t] = 0;
    float s0 = scores[row * NN + t];
    float r0 = relevance[row * NN + t];
    sv[t] = make_float2(s0, r0);
    __syncthreads();

    // histogram via ballots (4 atomics per warp, from lane 0)
    {
        int r0i = (int)r0;
        int h1 = __popc(__ballot_sync(~0u, r0i == 1));
        int h2 = __popc(__ballot_sync(~0u, r0i == 2));
        int h3 = __popc(__ballot_sync(~0u, r0i == 3));
        int h4 = __popc(__ballot_sync(~0u, r0i == 4));
        if ((t & 31) == 0) {
            atomicAdd(&counts[1], h1); atomicAdd(&counts[2], h2);
            atomicAdd(&counts[3], h3); atomicAdd(&counts[4], h4);
        }
    }

    // scan: score-rank + same-rel-lower-index count
    const int   i    = q * 64 + (t >> 3);
    const int   part = t & 7;
    const float2 self = sv[i];
    const float si  = self.x;
    const float rif = self.y;
    const int   thr = (i - part + 7) >> 3;    // #jj with 8jj+part < i

    int rk = 0, same = 0, jj = 0;
    #pragma unroll 8
    for (; jj < thr; ++jj) {                  // region j < i
        float2 v = sv[8 * jj + part];
        rk   += (v.x >= si);                  // (x>si) || (x==si && j<i)
        same += (v.y == rif);
    }
    #pragma unroll 8
    for (; jj < 64; ++jj)                     // region j >= i (incl. self)
        rk += (sv[8 * jj + part].x > si);

    int pk = rk | (same << 16);               // pack; no cross-field carry
    pk += __shfl_down_sync(0xffffffffu, pk, 4, 8);
    pk += __shfl_down_sync(0xffffffffu, pk, 2, 8);
    pk += __shfl_down_sync(0xffffffffu, pk, 1, 8);

    __syncthreads();                          // histogram complete
    const int c4 = counts[4], c3 = counts[3], c2 = counts[2], c1 = counts[1];

    if (part == 0) {
        int rkT   = pk & 0xffff;
        int sameT = pk >> 16;
        int r = (int)rif;
        int base = (r == 4) ? 0
                 : (r == 3) ? c4
                 : (r == 2) ? c4 + c3
                 : (r == 1) ? c4 + c3 + c2
                            : c4 + c3 + c2 + c1;
        int cr = (r == 4) ? c4 : (r == 3) ? c3 : (r == 2) ? c2
               : (r == 1) ? c1 : (NN - (c4 + c3 + c2 + c1));
        float g = (float)((1 << r) - 1);
        float d = __fdividef(1.0f, __log2f((float)(rkT + 3)));  // rank = rkT+1
        g_items[row * NN + base + sameT] =
            make_float4(g, d, __expf(si), __int_as_float(base + cr));
    }

    // Row constants (q==0 only; block-uniform branch)
    if (q == 0) {
        int b4 = c4, b3 = b4 + c3, b2 = b3 + c2, b1 = b2 + c1;
        float gl = t < b4 ? 15.f : t < b3 ? 7.f : t < b2 ? 3.f : t < b1 ? 1.f : 0.f;
        float v = __fdividef(gl, __log2f((float)(t + 2)));
        #pragma unroll
        for (int o = 16; o > 0; o >>= 1) v += __shfl_down_sync(0xffffffffu, v, o);
        if ((t & 31) == 0) wred[t >> 5] = v;
        __syncthreads();
        if (t == 0) {
            float idcg = 0.0f;
            #pragma unroll
            for (int k = 0; k < 16; ++k) idcg += wred[k];
            idcg = fmaxf(idcg, EPS);
            int c0 = NN - (c4 + c3 + c2 + c1);
            float sq = (float)c4 * c4 + (float)c3 * c3 + (float)c2 * c2 +
                       (float)c1 * c1 + (float)c0 * c0;
            float cntf = 0.5f * ((float)NN * NN - sq);
            g_rowScale[row] = 0.6931471805599453f /
                              (idcg * (cntf + EPS)) / (float)BB;
        }
    }
}

// ---------------- Kernel 2: valid pairs, warp-uniform bounds -------------------
// grid (16, 64), 256 threads. Thread owns sorted positions t and 511-t.
// lo non-decreasing in position -> warp lo from lane 0 (item A) / lane 31 (B);
// extra pairs clamp to exactly 0 via fmaxf. Uniform j -> broadcast LDS.128.
// Block c takes the c-th 1/16 of each range.
__global__ __launch_bounds__(256, 8)
void lr_pairs(float* __restrict__ out) {
    __shared__ float4 sj[NN];
    __shared__ float  ws[8];
    const int row = blockIdx.y;
    const int c   = blockIdx.x;      // 0..15
    const int t   = threadIdx.x;

    const float4* items = g_items + row * NN;
    sj[t]       = items[t];
    sj[t + 256] = items[t + 256];
    __syncthreads();

    float acc = 0.0f;

    {   // item A: position t (warp-uniform lo from lane 0)
        float4 mi = sj[t];
        int lou = __shfl_sync(0xffffffffu, __float_as_int(mi.w), 0);
        int len = NN - lou;
        int j0 = lou + ((c * len) >> 4);
        int j1 = lou + (((c + 1) * len) >> 4);
        float gi = mi.x, di = mi.y;
        float Ei = __fdividef(1.0f, mi.z);               // exp(-s_i)
        #pragma unroll 4
        for (int j = j0; j < j1; ++j) {
            float4 mj = sj[j];
            float w = fmaxf(gi - mj.x, 0.0f) * fabsf(di - mj.y);
            acc = fmaf(w, __log2f(fmaf(Ei, mj.z, 1.0f)), acc);
        }
    }
    {   // item B: position 511-t (warp-uniform lo from lane 31)
        float4 mi = sj[NN - 1 - t];
        int lou = __shfl_sync(0xffffffffu, __float_as_int(mi.w), 31);
        int len = NN - lou;
        int j0 = lou + ((c * len) >> 4);
        int j1 = lou + (((c + 1) * len) >> 4);
        float gi = mi.x, di = mi.y;
        float Ei = __fdividef(1.0f, mi.z);
        #pragma unroll 4
        for (int j = j0; j < j1; ++j) {
            float4 mj = sj[j];
            float w = fmaxf(gi - mj.x, 0.0f) * fabsf(di - mj.y);
            acc = fmaf(w, __log2f(fmaf(Ei, mj.z, 1.0f)), acc);
        }
    }

    // block reduce (8 warps)
    #pragma unroll
    for (int o = 16; o > 0; o >>= 1) acc += __shfl_down_sync(0xffffffffu, acc, o);
    if ((t & 31) == 0) ws[t >> 5] = acc;
    __syncthreads();
    if (t < 32) {
        float bs = (t < 8) ? ws[t] : 0.0f;
        #pragma unroll
        for (int o = 4; o > 0; o >>= 1) bs += __shfl_down_sync(0xffffffffu, bs, o);
        if (t == 0) {
            atomicAdd(&g_accum, bs * g_rowScale[row]);
            __threadfence();
            unsigned n = atomicAdd(&g_count, 1u);
            if (n == 16u * BB - 1u) {            // last block finalizes + resets
                out[0] = atomicAdd(&g_accum, 0.0f);
                g_accum = 0.0f;
                g_count = 0u;
            }
        }
    }
}

extern "C" void kernel_launch(void* const* d_in, const int* in_sizes, int n_in,
                              void* d_out, int out_size) {
    const float* scores    = (const float*)d_in[0];
    const float* relevance = (const float*)d_in[1];
    float* out = (float*)d_out;

    lr_prep<<<dim3(8, BB), 512>>>(scores, relevance);
    lr_pairs<<<dim3(16, BB), 256>>>(out);
}

// round 11
// speedup vs baseline: 1.0122x; 1.0122x over previous
#include <cuda_runtime.h>

#define BB 64
#define NN 512
#define EPS 1e-10f

// Scratch (allocation-free rule: __device__ globals)
// Items at RELEVANCE-SORTED positions: {disc, exp(score)}. Gains/bounds come
// from per-row bucket boundaries (g_rowB).
__device__ float2   g_items[BB * NN];
__device__ int4     g_rowB[BB];         // {b4, b3, b2, b1} cumulative bucket ends
__device__ float    g_rowScale[BB];     // ln2 / (idcg * (cnt+eps)) / B
__device__ float    g_accum = 0.0f;
__device__ unsigned g_count = 0u;

// ---------------- Kernel 1: ranks + sorted placement + row constants -----------
// grid (8, 64), 256 threads (R5's proven config). Block q owns items
// [q*64, q*64+64). 4 threads/item, j = 4*jj+part (adjacent float2 -> conflict-
// free). Tie-break (j < i) via loop split. Deterministic placement via
// same-rel scan packed with the rank count.
__global__ __launch_bounds__(256, 8)
void lr_prep(const float* __restrict__ scores,
             const float* __restrict__ relevance) {
    const int q   = blockIdx.x;
    const int row = blockIdx.y;
    const int t   = threadIdx.x;

    __shared__ float2 sv[NN];           // {score, rel}
    __shared__ int    counts[5];
    __shared__ float  wred[8];

    if (t < 5) counts[t] = 0;
    float s0 = scores[row * NN + t],    s1 = scores[row * NN + t + 256];
    float r0 = relevance[row * NN + t], r1 = relevance[row * NN + t + 256];
    sv[t]       = make_float2(s0, r0);
    sv[t + 256] = make_float2(s1, r1);
    __syncthreads();
    atomicAdd(&counts[(int)r0], 1);
    atomicAdd(&counts[(int)r1], 1);

    // scan: score-rank + same-rel-lower-index count
    const int   i    = q * 64 + (t >> 2);
    const int   part = t & 3;
    const float2 self = sv[i];
    const float si  = self.x;
    const float rif = self.y;
    const int   thr = (i - part + 3) >> 2;    // #jj with 4jj+part < i

    int rk = 0, same = 0, jj = 0;
    #pragma unroll 8
    for (; jj < thr; ++jj) {                  // region j < i
        float2 v = sv[4 * jj + part];
        rk   += (v.x >= si);                  // (x>si) || (x==si && j<i)
        same += (v.y == rif);
    }
    #pragma unroll 8
    for (; jj < 128; ++jj)                    // region j >= i (incl. self)
        rk += (sv[4 * jj + part].x > si);

    int pk = rk | (same << 16);               // pack; no cross-field carry
    pk += __shfl_down_sync(0xffffffffu, pk, 2, 4);
    pk += __shfl_down_sync(0xffffffffu, pk, 1, 4);

    __syncthreads();                          // histogram complete
    const int c4 = counts[4], c3 = counts[3], c2 = counts[2], c1 = counts[1];

    if (part == 0) {
        int rkT   = pk & 0xffff;
        int sameT = pk >> 16;
        int r = (int)rif;
        int base = (r == 4) ? 0
                 : (r == 3) ? c4
                 : (r == 2) ? c4 + c3
                 : (r == 1) ? c4 + c3 + c2
                            : c4 + c3 + c2 + c1;
        float d = __fdividef(1.0f, __log2f((float)(rkT + 3)));  // rank = rkT+1
        g_items[row * NN + base + sameT] = make_float2(d, __expf(si));
    }

    // Row constants (q==0 only; block-uniform branch)
    if (q == 0) {
        int b4 = c4, b3 = b4 + c3, b2 = b3 + c2, b1 = b2 + c1;
        float v = 0.0f;
        #pragma unroll
        for (int h = 0; h < 2; ++h) {
            int p = t + h * 256;
            float gl = p < b4 ? 15.f : p < b3 ? 7.f : p < b2 ? 3.f : p < b1 ? 1.f : 0.f;
            v += __fdividef(gl, __log2f((float)(p + 2)));
        }
        #pragma unroll
        for (int o = 16; o > 0; o >>= 1) v += __shfl_down_sync(0xffffffffu, v, o);
        if ((t & 31) == 0) wred[t >> 5] = v;
        __syncthreads();
        if (t == 0) {
            float idcg = fmaxf(wred[0] + wred[1] + wred[2] + wred[3] +
                               wred[4] + wred[5] + wred[6] + wred[7], EPS);
            int c0 = NN - (c4 + c3 + c2 + c1);
            float sq = (float)c4 * c4 + (float)c3 * c3 + (float)c2 * c2 +
                       (float)c1 * c1 + (float)c0 * c0;
            float cntf = 0.5f * ((float)NN * NN - sq);
            g_rowB[row] = make_int4(b4, b3, b2, b1);
            g_rowScale[row] = 0.6931471805599453f /
                              (idcg * (cntf + EPS)) / (float)BB;
        }
    }
}

// ---------------- Kernel 2: bucket-segmented valid pairs -----------------------
// grid (8, 64), 256 threads. Thread owns sorted positions t and 511-t.
// For each item, the j-range [lo_warp, 512) is tiled by bucket segments whose
// boundaries are row constants (warp-uniform). Gain difference is hoisted per
// segment: C = max(gi - G_s, 0); C==0 exactly for segments at/above the lane's
// bucket (absorbs warp-uniform range padding). Inner body: 5 instr/pair.
__global__ __launch_bounds__(256, 8)
void lr_pairs(float* __restrict__ out) {
    __shared__ float2 sde[NN];       // {disc, exp(score)} at sorted positions
    __shared__ int    stS[6];        // segment starts: {0, b4, b3, b2, b1, 512}
    __shared__ float  ws[8];
    const int row = blockIdx.y;
    const int c   = blockIdx.x;      // 0..7
    const int t   = threadIdx.x;

    reinterpret_cast<float4*>(sde)[t] =
        reinterpret_cast<const float4*>(g_items + row * NN)[t];
    if (t == 0) {
        int4 b = g_rowB[row];
        stS[0] = 0; stS[1] = b.x; stS[2] = b.y;
        stS[3] = b.z; stS[4] = b.w; stS[5] = NN;
    }
    __syncthreads();

    float acc = 0.0f;

    #pragma unroll
    for (int it = 0; it < 2; ++it) {
        const int p = it ? (NN - 1 - t) : t;
        // bucket index 0..4 (bucket b holds relevance 4-b)
        int bk = (p >= stS[1]) + (p >= stS[2]) + (p >= stS[3]) + (p >= stS[4]);
        float gi = (float)((16 >> bk) - 1);            // gain of own bucket
        // warp-min bucket: lane 0 (item A, ascending p) / lane 31 (item B)
        int bkw = __shfl_sync(0xffffffffu, bk, it ? 31 : 0);
        float2 me = sde[p];
        float di   = me.x;
        float Einv = __fdividef(1.0f, me.y);           // exp(-s_i)
        int lo  = stS[bkw + 1];                        // bkw==4 -> lo=512, len=0
        int len = NN - lo;
        int j0 = lo + ((c * len) >> 3);
        int j1 = lo + (((c + 1) * len) >> 3);

        for (int s = bkw + 1; s < 5; ++s) {            // warp-uniform segments
            int a = max(j0, stS[s]);
            int b = min(j1, stS[s + 1]);
            float C = fmaxf(gi - (float)((16 >> s) - 1), 0.0f);
            float part = 0.0f;
            #pragma unroll 4
            for (int j = a; j < b; ++j) {              // uniform j: broadcast LDS
                float2 v = sde[j];
                float dd = di - v.x;
                float lg = __log2f(fmaf(Einv, v.y, 1.0f));
                part = fmaf(fabsf(dd), lg, part);
            }
            acc = fmaf(C, part, acc);                  // gain diff per segment
        }
    }

    // block reduce (8 warps)
    #pragma unroll
    for (int o = 16; o > 0; o >>= 1) acc += __shfl_down_sync(0xffffffffu, acc, o);
    if ((t & 31) == 0) ws[t >> 5] = acc;
    __syncthreads();
    if (t < 32) {
        float bs = (t < 8) ? ws[t] : 0.0f;
        #pragma unroll
        for (int o = 4; o > 0; o >>= 1) bs += __shfl_down_sync(0xffffffffu, bs, o);
        if (t == 0) {
            atomicAdd(&g_accum, bs * g_rowScale[row]);
            __threadfence();
            unsigned n = atomicAdd(&g_count, 1u);
            if (n == 8u * BB - 1u) {             // last block finalizes + resets
                out[0] = atomicAdd(&g_accum, 0.0f);
                g_accum = 0.0f;
                g_count = 0u;
            }
        }
    }
}

extern "C" void kernel_launch(void* const* d_in, const int* in_sizes, int n_in,
                              void* d_out, int out_size) {
    const float* scores    = (const float*)d_in[0];
    const float* relevance = (const float*)d_in[1];
    float* out = (float*)d_out;

    lr_prep<<<dim3(8, BB), 256>>>(scores, relevance);
    lr_pairs<<<dim3(8, BB), 256>>>(out);
}

// round 12
// speedup vs baseline: 1.0640x; 1.0512x over previous
#include <cuda_runtime.h>

#define BB 64
#define NN 512
#define EPS 1e-10f

// Scratch (allocation-free rule: __device__ globals; zero-init at load,
// reset by the finalize block each run for graph replay)
__device__ float2   g_items[BB * NN];   // rel-sorted: {disc, exp(score)}
__device__ unsigned g_done[BB];         // per-row prep arrival counters
__device__ float    g_accum = 0.0f;
__device__ unsigned g_count = 0u;

// Single fused kernel. grid (8, 64), 256 threads, all 512 blocks co-resident.
// Phase 1: block q ranks items [q*64, q*64+64), writes {d, E} at rel-sorted
//          positions; EVERY block redundantly computes row constants (balanced).
// Row barrier: fence + arrive + poll on g_done[row] (threadFenceReduction).
// Phase 2: bucket-segmented valid pairs (5 instr/pair), warp-uniform bounds.
__global__ __launch_bounds__(256, 8)
void lr_fused(const float* __restrict__ scores,
              const float* __restrict__ relevance,
              float* __restrict__ out) {
    const int q   = blockIdx.x;      // 0..7
    const int row = blockIdx.y;
    const int t   = threadIdx.x;

    __shared__ float2 buf[NN];       // phase1: {score, rel}; phase2: {d, E}
    __shared__ int    counts[5];
    __shared__ int    stS[6];        // segment starts {0, b4, b3, b2, b1, 512}
    __shared__ float  wred[8];

    // ---------------- Phase 1: prep ----------------
    if (t < 5) counts[t] = 0;
    float s0 = scores[row * NN + t],    s1 = scores[row * NN + t + 256];
    float r0 = relevance[row * NN + t], r1 = relevance[row * NN + t + 256];
    buf[t]       = make_float2(s0, r0);
    buf[t + 256] = make_float2(s1, r1);
    __syncthreads();

    // histogram via ballots (4 atomics per warp, lane 0)
    {
        int a = (int)r0, b = (int)r1;
        int h1 = __popc(__ballot_sync(~0u, a == 1)) + __popc(__ballot_sync(~0u, b == 1));
        int h2 = __popc(__ballot_sync(~0u, a == 2)) + __popc(__ballot_sync(~0u, b == 2));
        int h3 = __popc(__ballot_sync(~0u, a == 3)) + __popc(__ballot_sync(~0u, b == 3));
        int h4 = __popc(__ballot_sync(~0u, a == 4)) + __popc(__ballot_sync(~0u, b == 4));
        if ((t & 31) == 0) {
            atomicAdd(&counts[1], h1); atomicAdd(&counts[2], h2);
            atomicAdd(&counts[3], h3); atomicAdd(&counts[4], h4);
        }
    }

    // rank scan: 4 thr/item, j = 4*jj+part; tie-break (j<i) via loop split
    const int   i    = q * 64 + (t >> 2);
    const int   part = t & 3;
    const float2 self = buf[i];
    const float si  = self.x;
    const float rif = self.y;
    const int   thr = (i - part + 3) >> 2;

    int rk = 0, same = 0, jj = 0;
    #pragma unroll 8
    for (; jj < thr; ++jj) {                  // region j < i
        float2 v = buf[4 * jj + part];
        rk   += (v.x >= si);
        same += (v.y == rif);
    }
    #pragma unroll 8
    for (; jj < 128; ++jj)                    // region j >= i
        rk += (buf[4 * jj + part].x > si);

    int pk = rk | (same << 16);
    pk += __shfl_down_sync(0xffffffffu, pk, 2, 4);
    pk += __shfl_down_sync(0xffffffffu, pk, 1, 4);

    __syncthreads();                          // histogram complete
    const int c4 = counts[4], c3 = counts[3], c2 = counts[2], c1 = counts[1];
    const int b4 = c4, b3 = b4 + c3, b2 = b3 + c2, b1 = b2 + c1;

    if (part == 0) {
        int rkT   = pk & 0xffff;
        int sameT = pk >> 16;
        int r = (int)rif;
        int base = (r == 4) ? 0 : (r == 3) ? b4 : (r == 2) ? b3
                 : (r == 1) ? b2 : b1;
        float d = __fdividef(1.0f, __log2f((float)(rkT + 3)));  // rank = rkT+1
        g_items[row * NN + base + sameT] = make_float2(d, __expf(si));
    }

    // row scale: redundant in EVERY block (balanced, no global round-trip)
    float scale = 0.0f;                       // valid on t==0
    {
        float v = 0.0f;
        #pragma unroll
        for (int h = 0; h < 2; ++h) {
            int p = t + h * 256;
            float gl = p < b4 ? 15.f : p < b3 ? 7.f : p < b2 ? 3.f : p < b1 ? 1.f : 0.f;
            v += __fdividef(gl, __log2f((float)(p + 2)));
        }
        #pragma unroll
        for (int o = 16; o > 0; o >>= 1) v += __shfl_down_sync(0xffffffffu, v, o);
        if ((t & 31) == 0) wred[t >> 5] = v;
        if (t == 0) {
            stS[0] = 0; stS[1] = b4; stS[2] = b3;
            stS[3] = b2; stS[4] = b1; stS[5] = NN;
        }
        __syncthreads();                      // also orders g_items stores
        if (t == 0) {
            float idcg = fmaxf(wred[0] + wred[1] + wred[2] + wred[3] +
                               wred[4] + wred[5] + wred[6] + wred[7], EPS);
            int c0 = NN - b1;
            float sq = (float)c4 * c4 + (float)c3 * c3 + (float)c2 * c2 +
                       (float)c1 * c1 + (float)c0 * c0;
            float cntf = 0.5f * ((float)NN * NN - sq);
            scale = 0.6931471805599453f / (idcg * (cntf + EPS)) / (float)BB;
        }
    }

    // ---------------- Row barrier ----------------
    if (t == 0) {
        __threadfence();
        atomicAdd(&g_done[row], 1u);
        while (atomicAdd(&g_done[row], 0u) < 8u) {}
    }
    __syncthreads();

    // ---------------- Phase 2: bucket-segmented valid pairs ----------------
    reinterpret_cast<float4*>(buf)[t] =
        __ldcg(reinterpret_cast<const float4*>(g_items + row * NN) + t);
    __syncthreads();

    float acc = 0.0f;
    #pragma unroll
    for (int it = 0; it < 2; ++it) {
        const int p = it ? (NN - 1 - t) : t;
        int bk = (p >= stS[1]) + (p >= stS[2]) + (p >= stS[3]) + (p >= stS[4]);
        float gi = (float)((16 >> bk) - 1);
        int bkw = __shfl_sync(0xffffffffu, bk, it ? 31 : 0);   // warp-min bucket
        float2 me = buf[p];
        float di   = me.x;
        float Einv = __fdividef(1.0f, me.y);                   // exp(-s_i)
        int lo  = stS[bkw + 1];                                // bkw==4 -> 512
        int len = NN - lo;
        int j0 = lo + ((q * len) >> 3);
        int j1 = lo + (((q + 1) * len) >> 3);

        for (int s = bkw + 1; s < 5; ++s) {                    // warp-uniform
            int a = max(j0, stS[s]);
            int b = min(j1, stS[s + 1]);
            float C = fmaxf(gi - (float)((16 >> s) - 1), 0.0f);
            float partsum = 0.0f;
            #pragma unroll 4
            for (int j = a; j < b; ++j) {                      // broadcast LDS
                float2 v = buf[j];
                float dd = di - v.x;
                float lg = __log2f(fmaf(Einv, v.y, 1.0f));
                partsum = fmaf(fabsf(dd), lg, partsum);
            }
            acc = fmaf(C, partsum, acc);
        }
    }

    // block reduce (8 warps)
    #pragma unroll
    for (int o = 16; o > 0; o >>= 1) acc += __shfl_down_sync(0xffffffffu, acc, o);
    if ((t & 31) == 0) wred[t >> 5] = acc;
    __syncthreads();
    if (t == 0) {
        float bs = wred[0] + wred[1] + wred[2] + wred[3] +
                   wred[4] + wred[5] + wred[6] + wred[7];
        atomicAdd(&g_accum, bs * scale);
        __threadfence();
        unsigned n = atomicAdd(&g_count, 1u);
        if (n == 8u * BB - 1u) {             // last block finalizes + resets
            out[0] = atomicAdd(&g_accum, 0.0f);
            g_accum = 0.0f;
            g_count = 0u;
            #pragma unroll
            for (int k = 0; k < BB; ++k) g_done[k] = 0u;
        }
    }
}

extern "C" void kernel_launch(void* const* d_in, const int* in_sizes, int n_in,
                              void* d_out, int out_size) {
    const float* scores    = (const float*)d_in[0];
    const float* relevance = (const float*)d_in[1];
    float* out = (float*)d_out;

    lr_fused<<<dim3(8, BB), 256>>>(scores, relevance, out);
}